// round 12
// baseline (speedup 1.0000x reference)
#include <cuda_runtime.h>
#include <cuda_fp16.h>
#include <cstdint>

#define B_  512
#define D_  1024
#define H1_ 512
#define H2_ 128

// ---- scratch (device globals: allocation-free rule) ----
__device__ float g_c1 [B_ * H1_];
__device__ float g_s1p[B_ * H1_];
__device__ float g_s2p[B_ * H2_];
__device__ float g_c3 [B_ * H1_];
__device__ float g_part1[4 * B_ * H1_];
__device__ float g_part2[4 * B_ * H2_];
__device__ __half g_b_frag[(size_t)D_ * H1_];
__device__ float  g_w2_frag[H2_ * H1_];
__device__ __half g_c3_frag[B_ * H1_];

__device__ __forceinline__ float sigm(float v) { return 1.0f / (1.0f + expf(-v)); }

__device__ __forceinline__ uint32_t packh2(float a, float b) {
    __half2 t = __floats2half2_rn(a, b);
    return *reinterpret_cast<uint32_t*>(&t);
}
__device__ __forceinline__ void mma_f16(float* c, const uint32_t* a,
                                        uint32_t b0, uint32_t b1) {
    asm volatile("mma.sync.aligned.m16n8k16.row.col.f32.f16.f16.f32 "
                 "{%0,%1,%2,%3}, {%4,%5,%6,%7}, {%8,%9}, {%0,%1,%2,%3};"
                 : "+f"(c[0]), "+f"(c[1]), "+f"(c[2]), "+f"(c[3])
                 : "r"(a[0]), "r"(a[1]), "r"(a[2]), "r"(a[3]), "r"(b0), "r"(b1));
}

// ============================================================================
// B fragment pack: W1 [H1 (k), D (n)] f32 -> g_b_frag (tile = 512B).
// ============================================================================
__global__ __launch_bounds__(256)
void w1_frag_kernel(const float* __restrict__ W1, __half* __restrict__ gB) {
    const int t = blockIdx.x * 8 + (threadIdx.x >> 5);
    const int n16 = t >> 5, kt = t & 31;
    const int lane = threadIdx.x & 31;
    const int n0 = n16 * 16 + (lane >> 2);
    const int kb = kt * 16 + 2 * (lane & 3);

    const float* Wk0 = W1 + (size_t)kb * D_;
    uint32_t p0 = packh2(Wk0[n0],              Wk0[D_ + n0]);
    uint32_t p1 = packh2(Wk0[8 * D_ + n0],     Wk0[9 * D_ + n0]);
    uint32_t p2 = packh2(Wk0[n0 + 8],          Wk0[D_ + n0 + 8]);
    uint32_t p3 = packh2(Wk0[8 * D_ + n0 + 8], Wk0[9 * D_ + n0 + 8]);

    *(uint4*)(gB + (size_t)t * 256 + lane * 8) = make_uint4(p0, p1, p2, p3);
}

// ============================================================================
// W2 fragment pre-permute (input-only, once). Layout [kt=32][mt=8], 1KB/tile.
// ============================================================================
__global__ __launch_bounds__(256)
void w2_frag_kernel(const float* __restrict__ W2, float* __restrict__ w2f) {
    const int kt = blockIdx.x;
    const int mt = threadIdx.x >> 5;
    const int lane = threadIdx.x & 31;
    const int r0 = mt * 16 + (lane >> 2);
    const int kb = kt * 16 + 2 * (lane & 3);
    const float* w2a = W2 + (size_t)r0 * H1_;
    const float* w2b = w2a + 8 * H1_;
    float* dst = w2f + ((size_t)kt * 8 + mt) * 256 + lane * 8;
    *(float4*)(dst)     = make_float4(w2a[kb],     w2a[kb + 1], w2b[kb],     w2b[kb + 1]);
    *(float4*)(dst + 4) = make_float4(w2a[kb + 8], w2a[kb + 9], w2b[kb + 8], w2b[kb + 9]);
}

// ============================================================================
// c3 fragment pack: c3 [512,512] f32 -> A-fragments [kt=32][mt=32].
// ============================================================================
__global__ __launch_bounds__(256)
void c3_frag_kernel(const float* __restrict__ c3, __half* __restrict__ gA) {
    const int t = blockIdx.x * 8 + (threadIdx.x >> 5);
    const int kt = t >> 5, mt = t & 31;
    const int lane = threadIdx.x & 31;
    const int r0 = mt * 16 + (lane >> 2);
    const int kb = kt * 16 + 2 * (lane & 3);
    const float* ca = c3 + (size_t)r0 * H1_;
    const float* cb = ca + 8 * H1_;
    uint32_t p0 = packh2(ca[kb],     ca[kb + 1]);
    uint32_t p1 = packh2(cb[kb],     cb[kb + 1]);
    uint32_t p2 = packh2(ca[kb + 8], ca[kb + 9]);
    uint32_t p3 = packh2(cb[kb + 8], cb[kb + 9]);
    *(uint4*)(gA + (size_t)t * 256 + lane * 8) = make_uint4(p0, p1, p2, p3);
}

// ============================================================================
// Split-K partial SGEMM (TB): P[z][m][n] = sum_{k in chunk z} A[m,k]*B[n,k].
// ============================================================================
__global__ __launch_bounds__(256)
void sgemm_part_kernel(const float* __restrict__ A, const float* __restrict__ Bm,
                       float* __restrict__ P, int M, int N, int K) {
    constexpr int BM = 64, BN = 64, BK = 16;
    __shared__ __align__(16) float As[BK][BM + 4];
    __shared__ __align__(16) float Bs[BK][BN + 4];

    const int tid = threadIdx.x;
    const int m0 = blockIdx.y * BM;
    const int n0 = blockIdx.x * BN;
    const int kbase = blockIdx.z * (K / 4);

    const int ak = tid & 15;
    const int am = tid >> 4;
    const int rowBase = (tid >> 4) * 4;
    const int colBase = (tid & 15) * 4;

    float acc[4][4] = {};
    float ra[4], rb[4];
    const int NT = (K / 4) / BK;

    auto loadA = [&](int t) {
        const int kt = kbase + t * BK;
#pragma unroll
        for (int j = 0; j < 4; j++)
            ra[j] = A[(size_t)(m0 + am + 16 * j) * K + kt + ak];
    };
    auto loadB = [&](int t) {
        const int kt = kbase + t * BK;
#pragma unroll
        for (int j = 0; j < 4; j++)
            rb[j] = Bm[(size_t)(n0 + am + 16 * j) * K + kt + ak];
    };
    auto storeAB = [&]() {
#pragma unroll
        for (int j = 0; j < 4; j++) As[ak][am + 16 * j] = ra[j];
#pragma unroll
        for (int j = 0; j < 4; j++) Bs[ak][am + 16 * j] = rb[j];
    };

    loadA(0); loadB(0);
    storeAB();
    __syncthreads();

    for (int t = 0; t < NT; t++) {
        if (t + 1 < NT) { loadA(t + 1); loadB(t + 1); }
#pragma unroll
        for (int kk = 0; kk < BK; kk++) {
            float a[4], bq[4];
            *(float4*)a  = *(const float4*)&As[kk][rowBase];
            *(float4*)bq = *(const float4*)&Bs[kk][colBase];
#pragma unroll
            for (int i = 0; i < 4; i++)
#pragma unroll
                for (int j = 0; j < 4; j++)
                    acc[i][j] += a[i] * bq[j];
        }
        __syncthreads();
        if (t + 1 < NT) { storeAB(); __syncthreads(); }
    }

    float* Pz = P + (size_t)blockIdx.z * M * N;
#pragma unroll
    for (int i = 0; i < 4; i++) {
        const int row = m0 + rowBase + i;
#pragma unroll
        for (int j = 0; j < 4; j++)
            Pz[(size_t)row * N + n0 + colBase + j] = acc[i][j];
    }
}

// ============================================================================
// Reduce 4 partials + bias -> sigmoid (+ derivative).
// ============================================================================
__global__ __launch_bounds__(256)
void reduce_act_kernel(const float* __restrict__ P, const float* __restrict__ bias,
                       float* __restrict__ C, float* __restrict__ S,
                       int MN, int Nmask) {
    const int idx = (blockIdx.x * 256 + threadIdx.x) * 4;
    float4 v0 = *(const float4*)(P + idx);
    float4 v1 = *(const float4*)(P + MN + idx);
    float4 v2 = *(const float4*)(P + 2 * MN + idx);
    float4 v3 = *(const float4*)(P + 3 * MN + idx);
    float4 bb = *(const float4*)(bias + (idx & Nmask));
    float4 c;
    c.x = sigm(v0.x + v1.x + v2.x + v3.x + bb.x);
    c.y = sigm(v0.y + v1.y + v2.y + v3.y + bb.y);
    c.z = sigm(v0.z + v1.z + v2.z + v3.z + bb.z);
    c.w = sigm(v0.w + v1.w + v2.w + v3.w + bb.w);
    *(float4*)(C + idx) = c;
    if (S) {
        float4 s;
        s.x = c.x * (1.0f - c.x);
        s.y = c.y * (1.0f - c.y);
        s.z = c.z * (1.0f - c.z);
        s.w = c.w * (1.0f - c.w);
        *(float4*)(S + idx) = s;
    }
}

// ============================================================================
// Jac GEMM: warp tile 32x64, CTA tile 128x128, 2 CTAs/SM (4 warps/SMSP).
// A built on the fly from w2f (L1/L2-resident) and s1p (smem).
// grid (8, 512); 8 warps: wm = wid>>1 (32 rows), wn = wid&1 (64 cols).
// ============================================================================
__global__ __launch_bounds__(256, 2)
void jac_mma_kernel(const float* __restrict__ w2f,
                    const float* __restrict__ s1p,
                    const __half* __restrict__ gB,
                    const float* __restrict__ s2p,
                    float* __restrict__ jac) {
    __shared__ float ss[H1_];
    const int tid = threadIdx.x;
    const int wid = tid >> 5;
    const int lane = tid & 31;
    const int wm = wid >> 1;           // 0..3  (32 rows each)
    const int wn = wid & 1;            // 0..1  (64 cols each)
    const int b  = blockIdx.y;
    const int n0 = blockIdx.x * 128;

    for (int i = tid; i < H1_; i += 256) ss[i] = s1p[(size_t)b * H1_ + i];
    __syncthreads();

    const float* Aw = w2f + (size_t)(wm * 2) * 256 + lane * 8;
    const __half* Bb = gB + (size_t)((n0 >> 4) + wn * 4) * (32 * 256) + lane * 8;
    const int klo = 2 * (lane & 3);

    float acc[2][8][4] = {};

    #pragma unroll 2
    for (int kt = 0; kt < 32; kt++) {
        const int kb = kt * 16 + klo;
        const float s0 = ss[kb], s1v = ss[kb + 1];
        const float s8 = ss[kb + 8], s9 = ss[kb + 9];

        uint32_t a[2][4];
        uint4 bv[4];
#pragma unroll
        for (int mt = 0; mt < 2; mt++) {
            const float* src = Aw + ((size_t)kt * 8 + mt) * 256;
            float4 f0 = *(const float4*)(src);
            float4 f1 = *(const float4*)(src + 4);
            a[mt][0] = packh2(f0.x * s0, f0.y * s1v);
            a[mt][1] = packh2(f0.z * s0, f0.w * s1v);
            a[mt][2] = packh2(f1.x * s8, f1.y * s9);
            a[mt][3] = packh2(f1.z * s8, f1.w * s9);
        }
#pragma unroll
        for (int np = 0; np < 4; np++)
            bv[np] = *(const uint4*)(Bb + ((size_t)np * 32 + kt) * 256);
#pragma unroll
        for (int mt = 0; mt < 2; mt++) {
#pragma unroll
            for (int np = 0; np < 4; np++) {
                mma_f16(acc[mt][np * 2 + 0], a[mt], bv[np].x, bv[np].y);
                mma_f16(acc[mt][np * 2 + 1], a[mt], bv[np].z, bv[np].w);
            }
        }
    }

    const int g = lane >> 2;
    const int cq = 2 * (lane & 3);
#pragma unroll
    for (int mt = 0; mt < 2; mt++) {
        const int r0 = wm * 32 + mt * 16 + g;
        const float s0 = s2p[(size_t)b * H2_ + r0];
        const float s1 = s2p[(size_t)b * H2_ + r0 + 8];
        float* row0 = jac + ((size_t)b * H2_ + r0) * D_ + n0;
        float* row1 = row0 + 8 * D_;
#pragma unroll
        for (int nt = 0; nt < 8; nt++) {
            const int col = wn * 64 + nt * 8 + cq;
            *(float2*)(row0 + col) = make_float2(acc[mt][nt][0] * s0, acc[mt][nt][1] * s0);
            *(float2*)(row1 + col) = make_float2(acc[mt][nt][2] * s1, acc[mt][nt][3] * s1);
        }
    }
}

// ============================================================================
// recover = c3 @ W1 + b_r via fragment-direct mma; reuses g_b_frag.
// ============================================================================
__global__ __launch_bounds__(256, 1)
void recover_mma_kernel(const __half* __restrict__ gA,
                        const __half* __restrict__ gB,
                        const float* __restrict__ b_r,
                        float* __restrict__ out) {
    const int tid = threadIdx.x;
    const int wid = tid >> 5;
    const int lane = tid & 31;
    const int wm = wid >> 2;
    const int wn = wid & 3;
    const int m0 = blockIdx.y * 128;
    const int n0 = blockIdx.x * 256;

    const int mtb = (m0 >> 4) + wm * 4;
    const int n16base = (n0 >> 4) + wn * 4;

    float acc[4][8][4] = {};

    #pragma unroll 2
    for (int kt = 0; kt < 32; kt++) {
        uint4 av[4], bv[4];
#pragma unroll
        for (int mt = 0; mt < 4; mt++)
            av[mt] = *(const uint4*)(gA + ((size_t)kt * 32 + mtb + mt) * 256
                                     + lane * 8);
#pragma unroll
        for (int np = 0; np < 4; np++)
            bv[np] = *(const uint4*)(gB + ((size_t)(n16base + np) * 32 + kt) * 256
                                     + lane * 8);
#pragma unroll
        for (int mt = 0; mt < 4; mt++) {
            const uint32_t* ap = reinterpret_cast<const uint32_t*>(&av[mt]);
#pragma unroll
            for (int np = 0; np < 4; np++) {
                mma_f16(acc[mt][np * 2 + 0], ap, bv[np].x, bv[np].y);
                mma_f16(acc[mt][np * 2 + 1], ap, bv[np].z, bv[np].w);
            }
        }
    }

    const int g = lane >> 2;
    const int cq = 2 * (lane & 3);
#pragma unroll
    for (int mt = 0; mt < 4; mt++) {
        const int r0 = m0 + wm * 64 + mt * 16 + g;
        float* row0 = out + (size_t)r0 * D_ + n0;
        float* row1 = row0 + 8 * D_;
#pragma unroll
        for (int nt = 0; nt < 8; nt++) {
            const int col = wn * 64 + nt * 8 + cq;
            const float bc0 = b_r[n0 + col], bc1 = b_r[n0 + col + 1];
            *(float2*)(row0 + col) = make_float2(acc[mt][nt][0] + bc0, acc[mt][nt][1] + bc1);
            *(float2*)(row1 + col) = make_float2(acc[mt][nt][2] + bc0, acc[mt][nt][3] + bc1);
        }
    }
}

// ============================================================================
// Plain scalar SGEMM (gemm3 only: c3 = sigmoid(c2 @ W2 + b3), K=128).
// ============================================================================
__global__ __launch_bounds__(256)
void sgemm_nn_kernel(const float* __restrict__ A, const float* __restrict__ Bm,
                     const float* __restrict__ bias, float* __restrict__ C,
                     int M, int N, int K) {
    constexpr int BM = 64, BN = 64, BK = 16;
    __shared__ __align__(16) float As[BK][BM + 4];
    __shared__ __align__(16) float Bs[BK][BN + 4];

    const int tid = threadIdx.x;
    const int m0 = blockIdx.y * BM;
    const int n0 = blockIdx.x * BN;

    const int ak = tid & 15;
    const int am = tid >> 4;
    const int rowBase = (tid >> 4) * 4;
    const int colBase = (tid & 15) * 4;

    float acc[4][4] = {};
    float ra[4], rb[4];
    const int NT = K / BK;

    auto loadA = [&](int t) {
        const int kt = t * BK;
#pragma unroll
        for (int j = 0; j < 4; j++)
            ra[j] = A[(size_t)(m0 + am + 16 * j) * K + kt + ak];
    };
    auto loadB = [&](int t) {
        const int kt = t * BK;
#pragma unroll
        for (int j = 0; j < 4; j++)
            rb[j] = Bm[(size_t)(kt + (tid >> 6) + 4 * j) * N + n0 + (tid & 63)];
    };
    auto storeAB = [&]() {
#pragma unroll
        for (int j = 0; j < 4; j++) As[ak][am + 16 * j] = ra[j];
#pragma unroll
        for (int j = 0; j < 4; j++) Bs[(tid >> 6) + 4 * j][tid & 63] = rb[j];
    };

    loadA(0); loadB(0);
    storeAB();
    __syncthreads();

    for (int t = 0; t < NT; t++) {
        if (t + 1 < NT) { loadA(t + 1); loadB(t + 1); }
#pragma unroll
        for (int kk = 0; kk < BK; kk++) {
            float a[4], bq[4];
            *(float4*)a  = *(const float4*)&As[kk][rowBase];
            *(float4*)bq = *(const float4*)&Bs[kk][colBase];
#pragma unroll
            for (int i = 0; i < 4; i++)
#pragma unroll
                for (int j = 0; j < 4; j++)
                    acc[i][j] += a[i] * bq[j];
        }
        __syncthreads();
        if (t + 1 < NT) { storeAB(); __syncthreads(); }
    }

#pragma unroll
    for (int i = 0; i < 4; i++) {
        const int row = m0 + rowBase + i;
#pragma unroll
        for (int j = 0; j < 4; j++) {
            const int col = n0 + colBase + j;
            C[(size_t)row * N + col] = sigm(acc[i][j] + bias[col]);
        }
    }
}

// ============================================================================
// Streams/events (created once, on the first — non-captured — call).
// ============================================================================
struct Aux {
    cudaStream_t s1;
    cudaEvent_t e0, ew, e2, etail;
    Aux() {
        cudaStreamCreateWithFlags(&s1, cudaStreamNonBlocking);
        cudaEventCreateWithFlags(&e0,   cudaEventDisableTiming);
        cudaEventCreateWithFlags(&ew,   cudaEventDisableTiming);
        cudaEventCreateWithFlags(&e2,   cudaEventDisableTiming);
        cudaEventCreateWithFlags(&etail, cudaEventDisableTiming);
    }
};

extern "C" void kernel_launch(void* const* d_in, const int* in_sizes, int n_in,
                              void* d_out, int out_size) {
    const float* x   = (const float*)d_in[0];
    const float* W1  = (const float*)d_in[1];
    const float* b1  = (const float*)d_in[2];
    const float* W2  = (const float*)d_in[3];
    const float* b2  = (const float*)d_in[4];
    const float* b3  = (const float*)d_in[5];
    const float* b_r = (const float*)d_in[6];

    float* out     = (float*)d_out;
    float* recover = out;
    float* c2      = out + (size_t)B_ * D_;
    float* jac     = c2 + (size_t)B_ * H2_;

    float *c1, *s1p, *s2p, *c3, *w2f, *p1, *p2;
    __half *b_frag, *c3_frag;
    cudaGetSymbolAddress((void**)&c1,  g_c1);
    cudaGetSymbolAddress((void**)&s1p, g_s1p);
    cudaGetSymbolAddress((void**)&s2p, g_s2p);
    cudaGetSymbolAddress((void**)&c3,  g_c3);
    cudaGetSymbolAddress((void**)&w2f, g_w2_frag);
    cudaGetSymbolAddress((void**)&p1,  g_part1);
    cudaGetSymbolAddress((void**)&p2,  g_part2);
    cudaGetSymbolAddress((void**)&b_frag, g_b_frag);
    cudaGetSymbolAddress((void**)&c3_frag, g_c3_frag);

    static Aux aux;
    cudaStream_t s0 = 0, s1 = aux.s1;
    dim3 blk(256);

    // fork
    cudaEventRecord(aux.e0, s0);
    cudaStreamWaitEvent(s1, aux.e0, 0);

    // s1: input-only fragment preps
    w1_frag_kernel<<<(64 * 32) / 8, blk, 0, s1>>>(W1, b_frag);
    w2_frag_kernel<<<32, blk, 0, s1>>>(W2, w2f);
    cudaEventRecord(aux.ew, s1);

    // s0: gemm1 split-K -> reduce -> c1, s1p
    sgemm_part_kernel<<<dim3(H1_ / 64, B_ / 64, 4), blk, 0, s0>>>(
        x, W1, p1, B_, H1_, D_);
    reduce_act_kernel<<<(B_ * H1_) / 1024, blk, 0, s0>>>(
        p1, b1, c1, s1p, B_ * H1_, H1_ - 1);

    // s0: gemm2 split-K -> reduce -> c2, s2p
    sgemm_part_kernel<<<dim3(H2_ / 64, B_ / 64, 4), blk, 0, s0>>>(
        c1, W2, p2, B_, H2_, H1_);
    reduce_act_kernel<<<(B_ * H2_) / 1024, blk, 0, s0>>>(
        p2, b2, c2, s2p, B_ * H2_, H2_ - 1);
    cudaEventRecord(aux.e2, s0);

    // s1 tail: c3 chain + recover (hidden under jac)
    cudaStreamWaitEvent(s1, aux.e2, 0);
    sgemm_nn_kernel<<<dim3(H1_ / 64, B_ / 64), blk, 0, s1>>>(
        c2, W2, b3, c3, B_, H1_, H2_);
    c3_frag_kernel<<<(32 * 32) / 8, blk, 0, s1>>>(c3, c3_frag);
    recover_mma_kernel<<<dim3(D_ / 256, B_ / 128), blk, 0, s1>>>(
        c3_frag, b_frag, b_r, recover);
    cudaEventRecord(aux.etail, s1);

    // s0: jac (2 CTAs/SM, 4 warps/SMSP)
    cudaStreamWaitEvent(s0, aux.ew, 0);
    jac_mma_kernel<<<dim3(D_ / 128, B_), blk, 0, s0>>>(w2f, s1p, b_frag, s2p, jac);

    // join
    cudaStreamWaitEvent(s0, aux.etail, 0);
}

// round 13
// speedup vs baseline: 1.0405x; 1.0405x over previous
#include <cuda_runtime.h>
#include <cuda_fp16.h>
#include <cstdint>

#define B_  512
#define D_  1024
#define H1_ 512
#define H2_ 128

// ---- scratch (device globals: allocation-free rule) ----
__device__ float g_c2tmp[B_ * H2_];                    // (unused spare)
__device__ float g_c3 [B_ * H1_];
__device__ float g_part1[4 * B_ * H1_];                // gemm1 split-K partials
__device__ float g_part2[4 * B_ * H2_];                // gemm2 split-K partials
__device__ __half g_b_frag[(size_t)D_ * H1_];
__device__ float  g_w2_frag[H2_ * H1_];
__device__ __half g_c3_frag[B_ * H1_];

__device__ __forceinline__ float sigm(float v) { return 1.0f / (1.0f + expf(-v)); }

__device__ __forceinline__ uint32_t packh2(float a, float b) {
    __half2 t = __floats2half2_rn(a, b);
    return *reinterpret_cast<uint32_t*>(&t);
}
__device__ __forceinline__ void mma_f16(float* c, const uint32_t* a,
                                        uint32_t b0, uint32_t b1) {
    asm volatile("mma.sync.aligned.m16n8k16.row.col.f32.f16.f16.f32 "
                 "{%0,%1,%2,%3}, {%4,%5,%6,%7}, {%8,%9}, {%0,%1,%2,%3};"
                 : "+f"(c[0]), "+f"(c[1]), "+f"(c[2]), "+f"(c[3])
                 : "r"(a[0]), "r"(a[1]), "r"(a[2]), "r"(a[3]), "r"(b0), "r"(b1));
}

// ============================================================================
// B fragment pack: W1 [H1 (k), D (n)] f32 -> g_b_frag (tile = 512B).
// ============================================================================
__global__ __launch_bounds__(256)
void w1_frag_kernel(const float* __restrict__ W1, __half* __restrict__ gB) {
    const int t = blockIdx.x * 8 + (threadIdx.x >> 5);
    const int n16 = t >> 5, kt = t & 31;
    const int lane = threadIdx.x & 31;
    const int n0 = n16 * 16 + (lane >> 2);
    const int kb = kt * 16 + 2 * (lane & 3);

    const float* Wk0 = W1 + (size_t)kb * D_;
    uint32_t p0 = packh2(Wk0[n0],              Wk0[D_ + n0]);
    uint32_t p1 = packh2(Wk0[8 * D_ + n0],     Wk0[9 * D_ + n0]);
    uint32_t p2 = packh2(Wk0[n0 + 8],          Wk0[D_ + n0 + 8]);
    uint32_t p3 = packh2(Wk0[8 * D_ + n0 + 8], Wk0[9 * D_ + n0 + 8]);

    *(uint4*)(gB + (size_t)t * 256 + lane * 8) = make_uint4(p0, p1, p2, p3);
}

// ============================================================================
// W2 fragment pre-permute (input-only, once). Layout [kt=32][mt=8], 1KB/tile.
// ============================================================================
__global__ __launch_bounds__(256)
void w2_frag_kernel(const float* __restrict__ W2, float* __restrict__ w2f) {
    const int kt = blockIdx.x;
    const int mt = threadIdx.x >> 5;
    const int lane = threadIdx.x & 31;
    const int r0 = mt * 16 + (lane >> 2);
    const int kb = kt * 16 + 2 * (lane & 3);
    const float* w2a = W2 + (size_t)r0 * H1_;
    const float* w2b = w2a + 8 * H1_;
    float* dst = w2f + ((size_t)kt * 8 + mt) * 256 + lane * 8;
    *(float4*)(dst)     = make_float4(w2a[kb],     w2a[kb + 1], w2b[kb],     w2b[kb + 1]);
    *(float4*)(dst + 4) = make_float4(w2a[kb + 8], w2a[kb + 9], w2b[kb + 8], w2b[kb + 9]);
}

// ============================================================================
// c3 fragment pack: c3 [512,512] f32 -> A-fragments [kt=32][mt=32].
// ============================================================================
__global__ __launch_bounds__(256)
void c3_frag_kernel(const float* __restrict__ c3, __half* __restrict__ gA) {
    const int t = blockIdx.x * 8 + (threadIdx.x >> 5);
    const int kt = t >> 5, mt = t & 31;
    const int lane = threadIdx.x & 31;
    const int r0 = mt * 16 + (lane >> 2);
    const int kb = kt * 16 + 2 * (lane & 3);
    const float* ca = c3 + (size_t)r0 * H1_;
    const float* cb = ca + 8 * H1_;
    uint32_t p0 = packh2(ca[kb],     ca[kb + 1]);
    uint32_t p1 = packh2(cb[kb],     cb[kb + 1]);
    uint32_t p2 = packh2(ca[kb + 8], ca[kb + 9]);
    uint32_t p3 = packh2(cb[kb + 8], cb[kb + 9]);
    *(uint4*)(gA + (size_t)t * 256 + lane * 8) = make_uint4(p0, p1, p2, p3);
}

// ============================================================================
// Split-K partial SGEMM (TB): P[z][m][n] = sum_{k in chunk z} A[m,k]*B[n,k].
// Used for gemm1 (x @ W1^T).
// ============================================================================
__global__ __launch_bounds__(256)
void sgemm_part_kernel(const float* __restrict__ A, const float* __restrict__ Bm,
                       float* __restrict__ P, int M, int N, int K) {
    constexpr int BM = 64, BN = 64, BK = 16;
    __shared__ __align__(16) float As[BK][BM + 4];
    __shared__ __align__(16) float Bs[BK][BN + 4];

    const int tid = threadIdx.x;
    const int m0 = blockIdx.y * BM;
    const int n0 = blockIdx.x * BN;
    const int kbase = blockIdx.z * (K / 4);

    const int ak = tid & 15;
    const int am = tid >> 4;
    const int rowBase = (tid >> 4) * 4;
    const int colBase = (tid & 15) * 4;

    float acc[4][4] = {};
    float ra[4], rb[4];
    const int NT = (K / 4) / BK;

    auto loadA = [&](int t) {
        const int kt = kbase + t * BK;
#pragma unroll
        for (int j = 0; j < 4; j++)
            ra[j] = A[(size_t)(m0 + am + 16 * j) * K + kt + ak];
    };
    auto loadB = [&](int t) {
        const int kt = kbase + t * BK;
#pragma unroll
        for (int j = 0; j < 4; j++)
            rb[j] = Bm[(size_t)(n0 + am + 16 * j) * K + kt + ak];
    };
    auto storeAB = [&]() {
#pragma unroll
        for (int j = 0; j < 4; j++) As[ak][am + 16 * j] = ra[j];
#pragma unroll
        for (int j = 0; j < 4; j++) Bs[ak][am + 16 * j] = rb[j];
    };

    loadA(0); loadB(0);
    storeAB();
    __syncthreads();

    for (int t = 0; t < NT; t++) {
        if (t + 1 < NT) { loadA(t + 1); loadB(t + 1); }
#pragma unroll
        for (int kk = 0; kk < BK; kk++) {
            float a[4], bq[4];
            *(float4*)a  = *(const float4*)&As[kk][rowBase];
            *(float4*)bq = *(const float4*)&Bs[kk][colBase];
#pragma unroll
            for (int i = 0; i < 4; i++)
#pragma unroll
                for (int j = 0; j < 4; j++)
                    acc[i][j] += a[i] * bq[j];
        }
        __syncthreads();
        if (t + 1 < NT) { storeAB(); __syncthreads(); }
    }

    float* Pz = P + (size_t)blockIdx.z * M * N;
#pragma unroll
    for (int i = 0; i < 4; i++) {
        const int row = m0 + rowBase + i;
#pragma unroll
        for (int j = 0; j < 4; j++)
            Pz[(size_t)row * N + n0 + colBase + j] = acc[i][j];
    }
}

// ============================================================================
// gemm2 split-K with c1 computed ON THE FLY from p1 partials + b1 + sigmoid.
// C1[m,k] = sigm(p1[0]+p1[1]+p1[2]+p1[3]+b1[k]);  P2[z][m][n] = sum C1*W2[n,k].
// M=512 (b), N=128 (h2), K=512 (h1). grid (2, 8, 4).
// ============================================================================
__global__ __launch_bounds__(256)
void sgemm2_part_kernel(const float* __restrict__ p1, const float* __restrict__ b1v,
                        const float* __restrict__ W2, float* __restrict__ P) {
    constexpr int BM = 64, BN = 64, BK = 16;
    constexpr int M = B_, N = H2_, K = H1_;
    constexpr int MN1 = B_ * H1_;
    __shared__ __align__(16) float As[BK][BM + 4];
    __shared__ __align__(16) float Bs[BK][BN + 4];

    const int tid = threadIdx.x;
    const int m0 = blockIdx.y * BM;
    const int n0 = blockIdx.x * BN;
    const int kbase = blockIdx.z * (K / 4);

    const int ak = tid & 15;
    const int am = tid >> 4;
    const int rowBase = (tid >> 4) * 4;
    const int colBase = (tid & 15) * 4;

    float acc[4][4] = {};
    float ra[4], rb[4];
    const int NT = (K / 4) / BK;

    auto loadA = [&](int t) {
        const int col = kbase + t * BK + ak;
        const float bc = b1v[col];
#pragma unroll
        for (int j = 0; j < 4; j++) {
            const size_t off = (size_t)(m0 + am + 16 * j) * K + col;
            float v = p1[off] + p1[MN1 + off] + p1[2 * MN1 + off]
                    + p1[3 * MN1 + off] + bc;
            ra[j] = sigm(v);
        }
    };
    auto loadB = [&](int t) {
        const int kt = kbase + t * BK;
#pragma unroll
        for (int j = 0; j < 4; j++)
            rb[j] = W2[(size_t)(n0 + am + 16 * j) * K + kt + ak];
    };
    auto storeAB = [&]() {
#pragma unroll
        for (int j = 0; j < 4; j++) As[ak][am + 16 * j] = ra[j];
#pragma unroll
        for (int j = 0; j < 4; j++) Bs[ak][am + 16 * j] = rb[j];
    };

    loadA(0); loadB(0);
    storeAB();
    __syncthreads();

    for (int t = 0; t < NT; t++) {
        if (t + 1 < NT) { loadA(t + 1); loadB(t + 1); }
#pragma unroll
        for (int kk = 0; kk < BK; kk++) {
            float a[4], bq[4];
            *(float4*)a  = *(const float4*)&As[kk][rowBase];
            *(float4*)bq = *(const float4*)&Bs[kk][colBase];
#pragma unroll
            for (int i = 0; i < 4; i++)
#pragma unroll
                for (int j = 0; j < 4; j++)
                    acc[i][j] += a[i] * bq[j];
        }
        __syncthreads();
        if (t + 1 < NT) { storeAB(); __syncthreads(); }
    }

    float* Pz = P + (size_t)blockIdx.z * M * N;
#pragma unroll
    for (int i = 0; i < 4; i++) {
        const int row = m0 + rowBase + i;
#pragma unroll
        for (int j = 0; j < 4; j++)
            Pz[(size_t)row * N + n0 + colBase + j] = acc[i][j];
    }
}

// ============================================================================
// Reduce 4 partials + bias -> sigmoid (used only for c2 output, on s1).
// ============================================================================
__global__ __launch_bounds__(256)
void reduce_act_kernel(const float* __restrict__ P, const float* __restrict__ bias,
                       float* __restrict__ C, int MN, int Nmask) {
    const int idx = (blockIdx.x * 256 + threadIdx.x) * 4;
    float4 v0 = *(const float4*)(P + idx);
    float4 v1 = *(const float4*)(P + MN + idx);
    float4 v2 = *(const float4*)(P + 2 * MN + idx);
    float4 v3 = *(const float4*)(P + 3 * MN + idx);
    float4 bb = *(const float4*)(bias + (idx & Nmask));
    float4 c;
    c.x = sigm(v0.x + v1.x + v2.x + v3.x + bb.x);
    c.y = sigm(v0.y + v1.y + v2.y + v3.y + bb.y);
    c.z = sigm(v0.z + v1.z + v2.z + v3.z + bb.z);
    c.w = sigm(v0.w + v1.w + v2.w + v3.w + bb.w);
    *(float4*)(C + idx) = c;
}

// ============================================================================
// Jac GEMM (R11 config: warp tile 64x64, CTA 128x256, 1 CTA/SM).
// s1p and s2p computed IN-KERNEL from p1/p2 partials (prologue, smem).
// A built on the fly from w2f; B from g_b_frag. grid (4, 512).
// ============================================================================
__global__ __launch_bounds__(256, 1)
void jac_mma_kernel(const float* __restrict__ w2f,
                    const float* __restrict__ p1, const float* __restrict__ b1v,
                    const float* __restrict__ p2, const float* __restrict__ b2v,
                    const __half* __restrict__ gB,
                    float* __restrict__ jac) {
    __shared__ float ss[H1_];
    __shared__ float s2s[H2_];
    constexpr int MN1 = B_ * H1_;
    constexpr int MN2 = B_ * H2_;
    const int tid = threadIdx.x;
    const int wid = tid >> 5;
    const int lane = tid & 31;
    const int wm = wid >> 2;           // 0..1  (64 rows)
    const int wn = wid & 3;            // 0..3  (64 cols)
    const int b  = blockIdx.y;
    const int n0 = blockIdx.x * 256;

    // prologue: s1p and s2p from split-K partials
    for (int i = tid; i < H1_; i += 256) {
        const int off = b * H1_ + i;
        float v = p1[off] + p1[MN1 + off] + p1[2 * MN1 + off]
                + p1[3 * MN1 + off] + b1v[i];
        float c = sigm(v);
        ss[i] = c * (1.0f - c);
    }
    if (tid < H2_) {
        const int off = b * H2_ + tid;
        float v = p2[off] + p2[MN2 + off] + p2[2 * MN2 + off]
                + p2[3 * MN2 + off] + b2v[tid];
        float c = sigm(v);
        s2s[tid] = c * (1.0f - c);
    }
    __syncthreads();

    const float* Aw = w2f + (size_t)(wm * 4) * 256 + lane * 8;
    const __half* Bb = gB + (size_t)((n0 >> 4) + wn * 4) * (32 * 256) + lane * 8;
    const int klo = 2 * (lane & 3);

    float acc[4][8][4] = {};

    #pragma unroll 2
    for (int kt = 0; kt < 32; kt++) {
        const int kb = kt * 16 + klo;
        const float s0 = ss[kb], s1v = ss[kb + 1];
        const float s8 = ss[kb + 8], s9 = ss[kb + 9];

        uint32_t a[4][4];
        uint4 bv[4];
#pragma unroll
        for (int mt = 0; mt < 4; mt++) {
            const float* src = Aw + ((size_t)kt * 8 + mt) * 256;
            float4 f0 = *(const float4*)(src);
            float4 f1 = *(const float4*)(src + 4);
            a[mt][0] = packh2(f0.x * s0, f0.y * s1v);
            a[mt][1] = packh2(f0.z * s0, f0.w * s1v);
            a[mt][2] = packh2(f1.x * s8, f1.y * s9);
            a[mt][3] = packh2(f1.z * s8, f1.w * s9);
        }
#pragma unroll
        for (int np = 0; np < 4; np++)
            bv[np] = *(const uint4*)(Bb + ((size_t)np * 32 + kt) * 256);
#pragma unroll
        for (int mt = 0; mt < 4; mt++) {
#pragma unroll
            for (int np = 0; np < 4; np++) {
                mma_f16(acc[mt][np * 2 + 0], a[mt], bv[np].x, bv[np].y);
                mma_f16(acc[mt][np * 2 + 1], a[mt], bv[np].z, bv[np].w);
            }
        }
    }

    const int g = lane >> 2;
    const int cq = 2 * (lane & 3);
#pragma unroll
    for (int mt = 0; mt < 4; mt++) {
        const int r0 = wm * 64 + mt * 16 + g;
        const float s0 = s2s[r0];
        const float s1 = s2s[r0 + 8];
        float* row0 = jac + ((size_t)b * H2_ + r0) * D_ + n0;
        float* row1 = row0 + 8 * D_;
#pragma unroll
        for (int nt = 0; nt < 8; nt++) {
            const int col = wn * 64 + nt * 8 + cq;
            *(float2*)(row0 + col) = make_float2(acc[mt][nt][0] * s0, acc[mt][nt][1] * s0);
            *(float2*)(row1 + col) = make_float2(acc[mt][nt][2] * s1, acc[mt][nt][3] * s1);
        }
    }
}

// ============================================================================
// recover = c3 @ W1 + b_r via fragment-direct mma; reuses g_b_frag.
// ============================================================================
__global__ __launch_bounds__(256, 1)
void recover_mma_kernel(const __half* __restrict__ gA,
                        const __half* __restrict__ gB,
                        const float* __restrict__ b_r,
                        float* __restrict__ out) {
    const int tid = threadIdx.x;
    const int wid = tid >> 5;
    const int lane = tid & 31;
    const int wm = wid >> 2;
    const int wn = wid & 3;
    const int m0 = blockIdx.y * 128;
    const int n0 = blockIdx.x * 256;

    const int mtb = (m0 >> 4) + wm * 4;
    const int n16base = (n0 >> 4) + wn * 4;

    float acc[4][8][4] = {};

    #pragma unroll 2
    for (int kt = 0; kt < 32; kt++) {
        uint4 av[4], bv[4];
#pragma unroll
        for (int mt = 0; mt < 4; mt++)
            av[mt] = *(const uint4*)(gA + ((size_t)kt * 32 + mtb + mt) * 256
                                     + lane * 8);
#pragma unroll
        for (int np = 0; np < 4; np++)
            bv[np] = *(const uint4*)(gB + ((size_t)(n16base + np) * 32 + kt) * 256
                                     + lane * 8);
#pragma unroll
        for (int mt = 0; mt < 4; mt++) {
            const uint32_t* ap = reinterpret_cast<const uint32_t*>(&av[mt]);
#pragma unroll
            for (int np = 0; np < 4; np++) {
                mma_f16(acc[mt][np * 2 + 0], ap, bv[np].x, bv[np].y);
                mma_f16(acc[mt][np * 2 + 1], ap, bv[np].z, bv[np].w);
            }
        }
    }

    const int g = lane >> 2;
    const int cq = 2 * (lane & 3);
#pragma unroll
    for (int mt = 0; mt < 4; mt++) {
        const int r0 = m0 + wm * 64 + mt * 16 + g;
        float* row0 = out + (size_t)r0 * D_ + n0;
        float* row1 = row0 + 8 * D_;
#pragma unroll
        for (int nt = 0; nt < 8; nt++) {
            const int col = wn * 64 + nt * 8 + cq;
            const float bc0 = b_r[n0 + col], bc1 = b_r[n0 + col + 1];
            *(float2*)(row0 + col) = make_float2(acc[mt][nt][0] + bc0, acc[mt][nt][1] + bc1);
            *(float2*)(row1 + col) = make_float2(acc[mt][nt][2] + bc0, acc[mt][nt][3] + bc1);
        }
    }
}

// ============================================================================
// Plain scalar SGEMM (gemm3: c3 = sigmoid(c2 @ W2 + b3), K=128).
// ============================================================================
__global__ __launch_bounds__(256)
void sgemm_nn_kernel(const float* __restrict__ A, const float* __restrict__ Bm,
                     const float* __restrict__ bias, float* __restrict__ C,
                     int M, int N, int K) {
    constexpr int BM = 64, BN = 64, BK = 16;
    __shared__ __align__(16) float As[BK][BM + 4];
    __shared__ __align__(16) float Bs[BK][BN + 4];

    const int tid = threadIdx.x;
    const int m0 = blockIdx.y * BM;
    const int n0 = blockIdx.x * BN;

    const int ak = tid & 15;
    const int am = tid >> 4;
    const int rowBase = (tid >> 4) * 4;
    const int colBase = (tid & 15) * 4;

    float acc[4][4] = {};
    float ra[4], rb[4];
    const int NT = K / BK;

    auto loadA = [&](int t) {
        const int kt = t * BK;
#pragma unroll
        for (int j = 0; j < 4; j++)
            ra[j] = A[(size_t)(m0 + am + 16 * j) * K + kt + ak];
    };
    auto loadB = [&](int t) {
        const int kt = t * BK;
#pragma unroll
        for (int j = 0; j < 4; j++)
            rb[j] = Bm[(size_t)(kt + (tid >> 6) + 4 * j) * N + n0 + (tid & 63)];
    };
    auto storeAB = [&]() {
#pragma unroll
        for (int j = 0; j < 4; j++) As[ak][am + 16 * j] = ra[j];
#pragma unroll
        for (int j = 0; j < 4; j++) Bs[(tid >> 6) + 4 * j][tid & 63] = rb[j];
    };

    loadA(0); loadB(0);
    storeAB();
    __syncthreads();

    for (int t = 0; t < NT; t++) {
        if (t + 1 < NT) { loadA(t + 1); loadB(t + 1); }
#pragma unroll
        for (int kk = 0; kk < BK; kk++) {
            float a[4], bq[4];
            *(float4*)a  = *(const float4*)&As[kk][rowBase];
            *(float4*)bq = *(const float4*)&Bs[kk][colBase];
#pragma unroll
            for (int i = 0; i < 4; i++)
#pragma unroll
                for (int j = 0; j < 4; j++)
                    acc[i][j] += a[i] * bq[j];
        }
        __syncthreads();
        if (t + 1 < NT) { storeAB(); __syncthreads(); }
    }

#pragma unroll
    for (int i = 0; i < 4; i++) {
        const int row = m0 + rowBase + i;
#pragma unroll
        for (int j = 0; j < 4; j++) {
            const int col = n0 + colBase + j;
            C[(size_t)row * N + col] = sigm(acc[i][j] + bias[col]);
        }
    }
}

// ============================================================================
// Streams/events (created once, on the first — non-captured — call).
// ============================================================================
struct Aux {
    cudaStream_t s1;
    cudaEvent_t e0, ew, ep2, etail;
    Aux() {
        cudaStreamCreateWithFlags(&s1, cudaStreamNonBlocking);
        cudaEventCreateWithFlags(&e0,   cudaEventDisableTiming);
        cudaEventCreateWithFlags(&ew,   cudaEventDisableTiming);
        cudaEventCreateWithFlags(&ep2,  cudaEventDisableTiming);
        cudaEventCreateWithFlags(&etail, cudaEventDisableTiming);
    }
};

extern "C" void kernel_launch(void* const* d_in, const int* in_sizes, int n_in,
                              void* d_out, int out_size) {
    const float* x   = (const float*)d_in[0];
    const float* W1  = (const float*)d_in[1];
    const float* b1  = (const float*)d_in[2];
    const float* W2  = (const float*)d_in[3];
    const float* b2  = (const float*)d_in[4];
    const float* b3  = (const float*)d_in[5];
    const float* b_r = (const float*)d_in[6];

    float* out     = (float*)d_out;
    float* recover = out;
    float* c2      = out + (size_t)B_ * D_;
    float* jac     = c2 + (size_t)B_ * H2_;

    float *c3, *w2f, *p1, *p2;
    __half *b_frag, *c3_frag;
    cudaGetSymbolAddress((void**)&c3,  g_c3);
    cudaGetSymbolAddress((void**)&w2f, g_w2_frag);
    cudaGetSymbolAddress((void**)&p1,  g_part1);
    cudaGetSymbolAddress((void**)&p2,  g_part2);
    cudaGetSymbolAddress((void**)&b_frag, g_b_frag);
    cudaGetSymbolAddress((void**)&c3_frag, g_c3_frag);

    static Aux aux;
    cudaStream_t s0 = 0, s1 = aux.s1;
    dim3 blk(256);

    // fork
    cudaEventRecord(aux.e0, s0);
    cudaStreamWaitEvent(s1, aux.e0, 0);

    // s1: input-only fragment preps
    w1_frag_kernel<<<(64 * 32) / 8, blk, 0, s1>>>(W1, b_frag);
    w2_frag_kernel<<<32, blk, 0, s1>>>(W2, w2f);
    cudaEventRecord(aux.ew, s1);

    // s0: gemm1 split-K -> p1
    sgemm_part_kernel<<<dim3(H1_ / 64, B_ / 64, 4), blk, 0, s0>>>(
        x, W1, p1, B_, H1_, D_);

    // s0: gemm2 split-K with c1 on the fly from p1 -> p2
    sgemm2_part_kernel<<<dim3(H2_ / 64, B_ / 64, 4), blk, 0, s0>>>(
        p1, b1, W2, p2);
    cudaEventRecord(aux.ep2, s0);

    // s1 tail: c2 output + c3 chain + recover (hidden under jac)
    cudaStreamWaitEvent(s1, aux.ep2, 0);
    reduce_act_kernel<<<(B_ * H2_) / 1024, blk, 0, s1>>>(
        p2, b2, c2, B_ * H2_, H2_ - 1);
    sgemm_nn_kernel<<<dim3(H1_ / 64, B_ / 64), blk, 0, s1>>>(
        c2, W2, b3, c3, B_, H1_, H2_);
    c3_frag_kernel<<<(32 * 32) / 8, blk, 0, s1>>>(c3, c3_frag);
    recover_mma_kernel<<<dim3(D_ / 256, B_ / 128), blk, 0, s1>>>(
        c3_frag, b_frag, b_r, recover);
    cudaEventRecord(aux.etail, s1);

    // s0: jac (computes s1p/s2p in-kernel from p1/p2)
    cudaStreamWaitEvent(s0, aux.ew, 0);
    jac_mma_kernel<<<dim3(D_ / 256, B_), blk, 0, s0>>>(
        w2f, p1, b1, p2, b2, b_frag, jac);

    // join
    cudaStreamWaitEvent(s0, aux.etail, 0);
}

// round 14
// speedup vs baseline: 1.0709x; 1.0292x over previous
#include <cuda_runtime.h>
#include <cuda_fp16.h>
#include <cstdint>

#define B_  512
#define D_  1024
#define H1_ 512
#define H2_ 128

// ---- scratch (device globals: allocation-free rule) ----
__device__ float g_c1 [B_ * H1_];
__device__ float g_s1p[B_ * H1_];
__device__ float g_c3 [B_ * H1_];
__device__ float g_part2[4 * B_ * H2_];                // gemm2 split-K partials
__device__ __half g_b_frag[(size_t)D_ * H1_];          // W1 B-frags for jac/recover
__device__ float  g_w2_frag[H2_ * H1_];
__device__ __half g_c3_frag[B_ * H1_];
__device__ __half g_x_hi[(size_t)B_ * D_];             // x A-frags, hi/lo split
__device__ __half g_x_lo[(size_t)B_ * D_];
__device__ __half g_w1g1_hi[(size_t)H1_ * D_];         // W1 B-frags (gemm1 orient)
__device__ __half g_w1g1_lo[(size_t)H1_ * D_];

__device__ __forceinline__ float sigm(float v) { return 1.0f / (1.0f + expf(-v)); }

__device__ __forceinline__ uint32_t packh2(float a, float b) {
    __half2 t = __floats2half2_rn(a, b);
    return *reinterpret_cast<uint32_t*>(&t);
}
__device__ __forceinline__ void mma_f16(float* c, const uint32_t* a,
                                        uint32_t b0, uint32_t b1) {
    asm volatile("mma.sync.aligned.m16n8k16.row.col.f32.f16.f16.f32 "
                 "{%0,%1,%2,%3}, {%4,%5,%6,%7}, {%8,%9}, {%0,%1,%2,%3};"
                 : "+f"(c[0]), "+f"(c[1]), "+f"(c[2]), "+f"(c[3])
                 : "r"(a[0]), "r"(a[1]), "r"(a[2]), "r"(a[3]), "r"(b0), "r"(b1));
}

// ============================================================================
// x A-fragment pack with hi/lo fp16 split. Tiles [kt=64][mt=32], 512B each.
// grid 256, 1 warp per tile.
// ============================================================================
__global__ __launch_bounds__(256)
void x_frag_kernel(const float* __restrict__ x,
                   __half* __restrict__ xh, __half* __restrict__ xl) {
    const int t = blockIdx.x * 8 + (threadIdx.x >> 5);
    const int mt = t & 31, kt = t >> 5;
    const int lane = threadIdx.x & 31;
    const int r0 = mt * 16 + (lane >> 2);
    const int kb = kt * 16 + 2 * (lane & 3);
    const float* xa = x + (size_t)r0 * D_;
    const float* xb = xa + 8 * D_;
    float v[8] = {xa[kb], xa[kb + 1], xb[kb], xb[kb + 1],
                  xa[kb + 8], xa[kb + 9], xb[kb + 8], xb[kb + 9]};
    uint32_t hp[4], lp[4];
#pragma unroll
    for (int j = 0; j < 4; j++) {
        float a = v[2 * j], c = v[2 * j + 1];
        __half ha = __float2half_rn(a);
        __half hc = __float2half_rn(c);
        hp[j] = packh2(a, c);
        lp[j] = packh2(a - __half2float(ha), c - __half2float(hc));
    }
    *(uint4*)(xh + (size_t)t * 256 + lane * 8) = make_uint4(hp[0], hp[1], hp[2], hp[3]);
    *(uint4*)(xl + (size_t)t * 256 + lane * 8) = make_uint4(lp[0], lp[1], lp[2], lp[3]);
}

// ============================================================================
// W1 B-fragment pack for gemm1 (n=h1, k=d), hi/lo split. Tiles [n16=32][kt=64].
// Fully coalesced in W1 rows. grid 256.
// ============================================================================
__global__ __launch_bounds__(256)
void w1g1_frag_kernel(const float* __restrict__ W1,
                      __half* __restrict__ wh, __half* __restrict__ wl) {
    const int t = blockIdx.x * 8 + (threadIdx.x >> 5);
    const int kt = t & 63, n16 = t >> 6;
    const int lane = threadIdx.x & 31;
    const int n0 = n16 * 16 + (lane >> 2);
    const int kb = kt * 16 + 2 * (lane & 3);
    const float* wa = W1 + (size_t)n0 * D_;
    const float* wb = wa + 8 * D_;
    float v[8] = {wa[kb], wa[kb + 1], wa[kb + 8], wa[kb + 9],
                  wb[kb], wb[kb + 1], wb[kb + 8], wb[kb + 9]};
    uint32_t hp[4], lp[4];
#pragma unroll
    for (int j = 0; j < 4; j++) {
        float a = v[2 * j], c = v[2 * j + 1];
        __half ha = __float2half_rn(a);
        __half hc = __float2half_rn(c);
        hp[j] = packh2(a, c);
        lp[j] = packh2(a - __half2float(ha), c - __half2float(hc));
    }
    const size_t off = ((size_t)n16 * 64 + kt) * 256 + lane * 8;
    *(uint4*)(wh + off) = make_uint4(hp[0], hp[1], hp[2], hp[3]);
    *(uint4*)(wl + off) = make_uint4(lp[0], lp[1], lp[2], lp[3]);
}

// ============================================================================
// gemm1 via mma.sync fp16 3-pass (AhBh + AlBh + AhBl), f32 accum.
// c1 = sigmoid(x @ W1^T + b1), s1p = c1*(1-c1) fused in epilogue.
// CTA 32x64, warp tile 16x16, grid (8, 16) = 128 CTAs.
// ============================================================================
__global__ __launch_bounds__(256)
void gemm1_mma_kernel(const __half* __restrict__ xh, const __half* __restrict__ xl,
                      const __half* __restrict__ w1h, const __half* __restrict__ w1l,
                      const float* __restrict__ b1v,
                      float* __restrict__ c1, float* __restrict__ s1p) {
    const int tid = threadIdx.x;
    const int wid = tid >> 5;
    const int lane = tid & 31;
    const int wm = wid >> 2;           // 0..1
    const int wn = wid & 3;            // 0..3
    const int mtb = blockIdx.y * 2 + wm;     // 16-row tile (0..31)
    const int n16 = blockIdx.x * 4 + wn;     // 16-col tile (0..31)

    const __half* Ah = xh + (size_t)mtb * 256 + lane * 8;
    const __half* Al = xl + (size_t)mtb * 256 + lane * 8;
    const __half* Bh = w1h + (size_t)n16 * 64 * 256 + lane * 8;
    const __half* Bl = w1l + (size_t)n16 * 64 * 256 + lane * 8;

    float acc[2][4] = {};

    #pragma unroll 4
    for (int kt = 0; kt < 64; kt++) {
        uint4 ah = *(const uint4*)(Ah + (size_t)kt * 32 * 256);
        uint4 al = *(const uint4*)(Al + (size_t)kt * 32 * 256);
        uint4 bh = *(const uint4*)(Bh + (size_t)kt * 256);
        uint4 bl = *(const uint4*)(Bl + (size_t)kt * 256);
        const uint32_t* ap  = reinterpret_cast<const uint32_t*>(&ah);
        const uint32_t* alp = reinterpret_cast<const uint32_t*>(&al);
        mma_f16(acc[0], ap,  bh.x, bh.y);
        mma_f16(acc[1], ap,  bh.z, bh.w);
        mma_f16(acc[0], alp, bh.x, bh.y);
        mma_f16(acc[1], alp, bh.z, bh.w);
        mma_f16(acc[0], ap,  bl.x, bl.y);
        mma_f16(acc[1], ap,  bl.z, bl.w);
    }

    const int g = lane >> 2;
    const int cq = 2 * (lane & 3);
    const int r0 = mtb * 16 + g;
#pragma unroll
    for (int nt = 0; nt < 2; nt++) {
        const int col = n16 * 16 + nt * 8 + cq;
        const float b0 = b1v[col], b1c = b1v[col + 1];
        float cA = sigm(acc[nt][0] + b0);
        float cB = sigm(acc[nt][1] + b1c);
        float cC = sigm(acc[nt][2] + b0);
        float cD = sigm(acc[nt][3] + b1c);
        *(float2*)(c1  + (size_t)r0 * H1_ + col)       = make_float2(cA, cB);
        *(float2*)(c1  + (size_t)(r0 + 8) * H1_ + col) = make_float2(cC, cD);
        *(float2*)(s1p + (size_t)r0 * H1_ + col)       = make_float2(cA * (1.0f - cA), cB * (1.0f - cB));
        *(float2*)(s1p + (size_t)(r0 + 8) * H1_ + col) = make_float2(cC * (1.0f - cC), cD * (1.0f - cD));
    }
}

// ============================================================================
// B fragment pack: W1 [H1 (k), D (n)] f32 -> g_b_frag (jac/recover orient).
// ============================================================================
__global__ __launch_bounds__(256)
void w1_frag_kernel(const float* __restrict__ W1, __half* __restrict__ gB) {
    const int t = blockIdx.x * 8 + (threadIdx.x >> 5);
    const int n16 = t >> 5, kt = t & 31;
    const int lane = threadIdx.x & 31;
    const int n0 = n16 * 16 + (lane >> 2);
    const int kb = kt * 16 + 2 * (lane & 3);

    const float* Wk0 = W1 + (size_t)kb * D_;
    uint32_t p0 = packh2(Wk0[n0],              Wk0[D_ + n0]);
    uint32_t p1 = packh2(Wk0[8 * D_ + n0],     Wk0[9 * D_ + n0]);
    uint32_t p2 = packh2(Wk0[n0 + 8],          Wk0[D_ + n0 + 8]);
    uint32_t p3 = packh2(Wk0[8 * D_ + n0 + 8], Wk0[9 * D_ + n0 + 8]);

    *(uint4*)(gB + (size_t)t * 256 + lane * 8) = make_uint4(p0, p1, p2, p3);
}

// ============================================================================
// W2 fragment pre-permute (input-only, once). Layout [kt=32][mt=8], 1KB/tile.
// ============================================================================
__global__ __launch_bounds__(256)
void w2_frag_kernel(const float* __restrict__ W2, float* __restrict__ w2f) {
    const int kt = blockIdx.x;
    const int mt = threadIdx.x >> 5;
    const int lane = threadIdx.x & 31;
    const int r0 = mt * 16 + (lane >> 2);
    const int kb = kt * 16 + 2 * (lane & 3);
    const float* w2a = W2 + (size_t)r0 * H1_;
    const float* w2b = w2a + 8 * H1_;
    float* dst = w2f + ((size_t)kt * 8 + mt) * 256 + lane * 8;
    *(float4*)(dst)     = make_float4(w2a[kb],     w2a[kb + 1], w2b[kb],     w2b[kb + 1]);
    *(float4*)(dst + 4) = make_float4(w2a[kb + 8], w2a[kb + 9], w2b[kb + 8], w2b[kb + 9]);
}

// ============================================================================
// c3 fragment pack: c3 [512,512] f32 -> A-fragments [kt=32][mt=32].
// ============================================================================
__global__ __launch_bounds__(256)
void c3_frag_kernel(const float* __restrict__ c3, __half* __restrict__ gA) {
    const int t = blockIdx.x * 8 + (threadIdx.x >> 5);
    const int kt = t >> 5, mt = t & 31;
    const int lane = threadIdx.x & 31;
    const int r0 = mt * 16 + (lane >> 2);
    const int kb = kt * 16 + 2 * (lane & 3);
    const float* ca = c3 + (size_t)r0 * H1_;
    const float* cb = ca + 8 * H1_;
    uint32_t p0 = packh2(ca[kb],     ca[kb + 1]);
    uint32_t p1 = packh2(cb[kb],     cb[kb + 1]);
    uint32_t p2 = packh2(ca[kb + 8], ca[kb + 9]);
    uint32_t p3 = packh2(cb[kb + 8], cb[kb + 9]);
    *(uint4*)(gA + (size_t)t * 256 + lane * 8) = make_uint4(p0, p1, p2, p3);
}

// ============================================================================
// Split-K partial SGEMM (TB): P[z][m][n] = sum_{k in chunk z} A[m,k]*B[n,k].
// Used for gemm2 (c1 @ W2^T), reading materialized c1.
// ============================================================================
__global__ __launch_bounds__(256)
void sgemm_part_kernel(const float* __restrict__ A, const float* __restrict__ Bm,
                       float* __restrict__ P, int M, int N, int K) {
    constexpr int BM = 64, BN = 64, BK = 16;
    __shared__ __align__(16) float As[BK][BM + 4];
    __shared__ __align__(16) float Bs[BK][BN + 4];

    const int tid = threadIdx.x;
    const int m0 = blockIdx.y * BM;
    const int n0 = blockIdx.x * BN;
    const int kbase = blockIdx.z * (K / 4);

    const int ak = tid & 15;
    const int am = tid >> 4;
    const int rowBase = (tid >> 4) * 4;
    const int colBase = (tid & 15) * 4;

    float acc[4][4] = {};
    float ra[4], rb[4];
    const int NT = (K / 4) / BK;

    auto loadA = [&](int t) {
        const int kt = kbase + t * BK;
#pragma unroll
        for (int j = 0; j < 4; j++)
            ra[j] = A[(size_t)(m0 + am + 16 * j) * K + kt + ak];
    };
    auto loadB = [&](int t) {
        const int kt = kbase + t * BK;
#pragma unroll
        for (int j = 0; j < 4; j++)
            rb[j] = Bm[(size_t)(n0 + am + 16 * j) * K + kt + ak];
    };
    auto storeAB = [&]() {
#pragma unroll
        for (int j = 0; j < 4; j++) As[ak][am + 16 * j] = ra[j];
#pragma unroll
        for (int j = 0; j < 4; j++) Bs[ak][am + 16 * j] = rb[j];
    };

    loadA(0); loadB(0);
    storeAB();
    __syncthreads();

    for (int t = 0; t < NT; t++) {
        if (t + 1 < NT) { loadA(t + 1); loadB(t + 1); }
#pragma unroll
        for (int kk = 0; kk < BK; kk++) {
            float a[4], bq[4];
            *(float4*)a  = *(const float4*)&As[kk][rowBase];
            *(float4*)bq = *(const float4*)&Bs[kk][colBase];
#pragma unroll
            for (int i = 0; i < 4; i++)
#pragma unroll
                for (int j = 0; j < 4; j++)
                    acc[i][j] += a[i] * bq[j];
        }
        __syncthreads();
        if (t + 1 < NT) { storeAB(); __syncthreads(); }
    }

    float* Pz = P + (size_t)blockIdx.z * M * N;
#pragma unroll
    for (int i = 0; i < 4; i++) {
        const int row = m0 + rowBase + i;
#pragma unroll
        for (int j = 0; j < 4; j++)
            Pz[(size_t)row * N + n0 + colBase + j] = acc[i][j];
    }
}

// ============================================================================
// Reduce 4 partials + bias -> sigmoid (c2 output, on s1).
// ============================================================================
__global__ __launch_bounds__(256)
void reduce_act_kernel(const float* __restrict__ P, const float* __restrict__ bias,
                       float* __restrict__ C, int MN, int Nmask) {
    const int idx = (blockIdx.x * 256 + threadIdx.x) * 4;
    float4 v0 = *(const float4*)(P + idx);
    float4 v1 = *(const float4*)(P + MN + idx);
    float4 v2 = *(const float4*)(P + 2 * MN + idx);
    float4 v3 = *(const float4*)(P + 3 * MN + idx);
    float4 bb = *(const float4*)(bias + (idx & Nmask));
    float4 c;
    c.x = sigm(v0.x + v1.x + v2.x + v3.x + bb.x);
    c.y = sigm(v0.y + v1.y + v2.y + v3.y + bb.y);
    c.z = sigm(v0.z + v1.z + v2.z + v3.z + bb.z);
    c.w = sigm(v0.w + v1.w + v2.w + v3.w + bb.w);
    *(float4*)(C + idx) = c;
}

// ============================================================================
// Jac GEMM (R11 config: warp 64x64, CTA 128x256, 1 CTA/SM). s1p loaded
// directly; s2p computed in prologue from p2 partials. grid (4, 512).
// ============================================================================
__global__ __launch_bounds__(256, 1)
void jac_mma_kernel(const float* __restrict__ w2f,
                    const float* __restrict__ s1p,
                    const float* __restrict__ p2, const float* __restrict__ b2v,
                    const __half* __restrict__ gB,
                    float* __restrict__ jac) {
    __shared__ float ss[H1_];
    __shared__ float s2s[H2_];
    constexpr int MN2 = B_ * H2_;
    const int tid = threadIdx.x;
    const int wid = tid >> 5;
    const int lane = tid & 31;
    const int wm = wid >> 2;
    const int wn = wid & 3;
    const int b  = blockIdx.y;
    const int n0 = blockIdx.x * 256;

    for (int i = tid; i < H1_; i += 256) ss[i] = s1p[(size_t)b * H1_ + i];
    if (tid < H2_) {
        const int off = b * H2_ + tid;
        float v = p2[off] + p2[MN2 + off] + p2[2 * MN2 + off]
                + p2[3 * MN2 + off] + b2v[tid];
        float c = sigm(v);
        s2s[tid] = c * (1.0f - c);
    }
    __syncthreads();

    const float* Aw = w2f + (size_t)(wm * 4) * 256 + lane * 8;
    const __half* Bb = gB + (size_t)((n0 >> 4) + wn * 4) * (32 * 256) + lane * 8;
    const int klo = 2 * (lane & 3);

    float acc[4][8][4] = {};

    #pragma unroll 2
    for (int kt = 0; kt < 32; kt++) {
        const int kb = kt * 16 + klo;
        const float s0 = ss[kb], s1v = ss[kb + 1];
        const float s8 = ss[kb + 8], s9 = ss[kb + 9];

        uint32_t a[4][4];
        uint4 bv[4];
#pragma unroll
        for (int mt = 0; mt < 4; mt++) {
            const float* src = Aw + ((size_t)kt * 8 + mt) * 256;
            float4 f0 = *(const float4*)(src);
            float4 f1 = *(const float4*)(src + 4);
            a[mt][0] = packh2(f0.x * s0, f0.y * s1v);
            a[mt][1] = packh2(f0.z * s0, f0.w * s1v);
            a[mt][2] = packh2(f1.x * s8, f1.y * s9);
            a[mt][3] = packh2(f1.z * s8, f1.w * s9);
        }
#pragma unroll
        for (int np = 0; np < 4; np++)
            bv[np] = *(const uint4*)(Bb + ((size_t)np * 32 + kt) * 256);
#pragma unroll
        for (int mt = 0; mt < 4; mt++) {
#pragma unroll
            for (int np = 0; np < 4; np++) {
                mma_f16(acc[mt][np * 2 + 0], a[mt], bv[np].x, bv[np].y);
                mma_f16(acc[mt][np * 2 + 1], a[mt], bv[np].z, bv[np].w);
            }
        }
    }

    const int g = lane >> 2;
    const int cq = 2 * (lane & 3);
#pragma unroll
    for (int mt = 0; mt < 4; mt++) {
        const int r0 = wm * 64 + mt * 16 + g;
        const float s0 = s2s[r0];
        const float s1 = s2s[r0 + 8];
        float* row0 = jac + ((size_t)b * H2_ + r0) * D_ + n0;
        float* row1 = row0 + 8 * D_;
#pragma unroll
        for (int nt = 0; nt < 8; nt++) {
            const int col = wn * 64 + nt * 8 + cq;
            *(float2*)(row0 + col) = make_float2(acc[mt][nt][0] * s0, acc[mt][nt][1] * s0);
            *(float2*)(row1 + col) = make_float2(acc[mt][nt][2] * s1, acc[mt][nt][3] * s1);
        }
    }
}

// ============================================================================
// recover = c3 @ W1 + b_r via fragment-direct mma; reuses g_b_frag.
// ============================================================================
__global__ __launch_bounds__(256, 1)
void recover_mma_kernel(const __half* __restrict__ gA,
                        const __half* __restrict__ gB,
                        const float* __restrict__ b_r,
                        float* __restrict__ out) {
    const int tid = threadIdx.x;
    const int wid = tid >> 5;
    const int lane = tid & 31;
    const int wm = wid >> 2;
    const int wn = wid & 3;
    const int m0 = blockIdx.y * 128;
    const int n0 = blockIdx.x * 256;

    const int mtb = (m0 >> 4) + wm * 4;
    const int n16base = (n0 >> 4) + wn * 4;

    float acc[4][8][4] = {};

    #pragma unroll 2
    for (int kt = 0; kt < 32; kt++) {
        uint4 av[4], bv[4];
#pragma unroll
        for (int mt = 0; mt < 4; mt++)
            av[mt] = *(const uint4*)(gA + ((size_t)kt * 32 + mtb + mt) * 256
                                     + lane * 8);
#pragma unroll
        for (int np = 0; np < 4; np++)
            bv[np] = *(const uint4*)(gB + ((size_t)(n16base + np) * 32 + kt) * 256
                                     + lane * 8);
#pragma unroll
        for (int mt = 0; mt < 4; mt++) {
            const uint32_t* ap = reinterpret_cast<const uint32_t*>(&av[mt]);
#pragma unroll
            for (int np = 0; np < 4; np++) {
                mma_f16(acc[mt][np * 2 + 0], ap, bv[np].x, bv[np].y);
                mma_f16(acc[mt][np * 2 + 1], ap, bv[np].z, bv[np].w);
            }
        }
    }

    const int g = lane >> 2;
    const int cq = 2 * (lane & 3);
#pragma unroll
    for (int mt = 0; mt < 4; mt++) {
        const int r0 = m0 + wm * 64 + mt * 16 + g;
        float* row0 = out + (size_t)r0 * D_ + n0;
        float* row1 = row0 + 8 * D_;
#pragma unroll
        for (int nt = 0; nt < 8; nt++) {
            const int col = wn * 64 + nt * 8 + cq;
            const float bc0 = b_r[n0 + col], bc1 = b_r[n0 + col + 1];
            *(float2*)(row0 + col) = make_float2(acc[mt][nt][0] + bc0, acc[mt][nt][1] + bc1);
            *(float2*)(row1 + col) = make_float2(acc[mt][nt][2] + bc0, acc[mt][nt][3] + bc1);
        }
    }
}

// ============================================================================
// Plain scalar SGEMM (gemm3: c3 = sigmoid(c2 @ W2 + b3), K=128).
// ============================================================================
__global__ __launch_bounds__(256)
void sgemm_nn_kernel(const float* __restrict__ A, const float* __restrict__ Bm,
                     const float* __restrict__ bias, float* __restrict__ C,
                     int M, int N, int K) {
    constexpr int BM = 64, BN = 64, BK = 16;
    __shared__ __align__(16) float As[BK][BM + 4];
    __shared__ __align__(16) float Bs[BK][BN + 4];

    const int tid = threadIdx.x;
    const int m0 = blockIdx.y * BM;
    const int n0 = blockIdx.x * BN;

    const int ak = tid & 15;
    const int am = tid >> 4;
    const int rowBase = (tid >> 4) * 4;
    const int colBase = (tid & 15) * 4;

    float acc[4][4] = {};
    float ra[4], rb[4];
    const int NT = K / BK;

    auto loadA = [&](int t) {
        const int kt = t * BK;
#pragma unroll
        for (int j = 0; j < 4; j++)
            ra[j] = A[(size_t)(m0 + am + 16 * j) * K + kt + ak];
    };
    auto loadB = [&](int t) {
        const int kt = t * BK;
#pragma unroll
        for (int j = 0; j < 4; j++)
            rb[j] = Bm[(size_t)(kt + (tid >> 6) + 4 * j) * N + n0 + (tid & 63)];
    };
    auto storeAB = [&]() {
#pragma unroll
        for (int j = 0; j < 4; j++) As[ak][am + 16 * j] = ra[j];
#pragma unroll
        for (int j = 0; j < 4; j++) Bs[(tid >> 6) + 4 * j][tid & 63] = rb[j];
    };

    loadA(0); loadB(0);
    storeAB();
    __syncthreads();

    for (int t = 0; t < NT; t++) {
        if (t + 1 < NT) { loadA(t + 1); loadB(t + 1); }
#pragma unroll
        for (int kk = 0; kk < BK; kk++) {
            float a[4], bq[4];
            *(float4*)a  = *(const float4*)&As[kk][rowBase];
            *(float4*)bq = *(const float4*)&Bs[kk][colBase];
#pragma unroll
            for (int i = 0; i < 4; i++)
#pragma unroll
                for (int j = 0; j < 4; j++)
                    acc[i][j] += a[i] * bq[j];
        }
        __syncthreads();
        if (t + 1 < NT) { storeAB(); __syncthreads(); }
    }

#pragma unroll
    for (int i = 0; i < 4; i++) {
        const int row = m0 + rowBase + i;
#pragma unroll
        for (int j = 0; j < 4; j++) {
            const int col = n0 + colBase + j;
            C[(size_t)row * N + col] = sigm(acc[i][j] + bias[col]);
        }
    }
}

// ============================================================================
// Streams/events (created once, on the first — non-captured — call).
// ============================================================================
struct Aux {
    cudaStream_t s1;
    cudaEvent_t e0, eg1, ew, ep2, etail;
    Aux() {
        cudaStreamCreateWithFlags(&s1, cudaStreamNonBlocking);
        cudaEventCreateWithFlags(&e0,   cudaEventDisableTiming);
        cudaEventCreateWithFlags(&eg1,  cudaEventDisableTiming);
        cudaEventCreateWithFlags(&ew,   cudaEventDisableTiming);
        cudaEventCreateWithFlags(&ep2,  cudaEventDisableTiming);
        cudaEventCreateWithFlags(&etail, cudaEventDisableTiming);
    }
};

extern "C" void kernel_launch(void* const* d_in, const int* in_sizes, int n_in,
                              void* d_out, int out_size) {
    const float* x   = (const float*)d_in[0];
    const float* W1  = (const float*)d_in[1];
    const float* b1  = (const float*)d_in[2];
    const float* W2  = (const float*)d_in[3];
    const float* b2  = (const float*)d_in[4];
    const float* b3  = (const float*)d_in[5];
    const float* b_r = (const float*)d_in[6];

    float* out     = (float*)d_out;
    float* recover = out;
    float* c2      = out + (size_t)B_ * D_;
    float* jac     = c2 + (size_t)B_ * H2_;

    float *c1, *s1p, *c3, *w2f, *p2;
    __half *b_frag, *c3_frag, *xh, *xl, *w1g1h, *w1g1l;
    cudaGetSymbolAddress((void**)&c1,  g_c1);
    cudaGetSymbolAddress((void**)&s1p, g_s1p);
    cudaGetSymbolAddress((void**)&c3,  g_c3);
    cudaGetSymbolAddress((void**)&w2f, g_w2_frag);
    cudaGetSymbolAddress((void**)&p2,  g_part2);
    cudaGetSymbolAddress((void**)&b_frag, g_b_frag);
    cudaGetSymbolAddress((void**)&c3_frag, g_c3_frag);
    cudaGetSymbolAddress((void**)&xh, g_x_hi);
    cudaGetSymbolAddress((void**)&xl, g_x_lo);
    cudaGetSymbolAddress((void**)&w1g1h, g_w1g1_hi);
    cudaGetSymbolAddress((void**)&w1g1l, g_w1g1_lo);

    static Aux aux;
    cudaStream_t s0 = 0, s1 = aux.s1;
    dim3 blk(256);

    // fork
    cudaEventRecord(aux.e0, s0);
    cudaStreamWaitEvent(s1, aux.e0, 0);

    // s1: input-only fragment preps (gemm1 B first — needed earliest)
    w1g1_frag_kernel<<<256, blk, 0, s1>>>(W1, w1g1h, w1g1l);
    cudaEventRecord(aux.eg1, s1);
    w1_frag_kernel<<<(64 * 32) / 8, blk, 0, s1>>>(W1, b_frag);
    w2_frag_kernel<<<32, blk, 0, s1>>>(W2, w2f);
    cudaEventRecord(aux.ew, s1);

    // s0: x fragments (independent), then gemm1 on HMMA -> c1, s1p
    x_frag_kernel<<<256, blk, 0, s0>>>(x, xh, xl);
    cudaStreamWaitEvent(s0, aux.eg1, 0);
    gemm1_mma_kernel<<<dim3(8, 16), blk, 0, s0>>>(xh, xl, w1g1h, w1g1l,
                                                  b1, c1, s1p);

    // s0: gemm2 split-K on materialized c1 -> p2
    sgemm_part_kernel<<<dim3(H2_ / 64, B_ / 64, 4), blk, 0, s0>>>(
        c1, W2, p2, B_, H2_, H1_);
    cudaEventRecord(aux.ep2, s0);

    // s1 tail: c2 output + c3 chain + recover (hidden under jac)
    cudaStreamWaitEvent(s1, aux.ep2, 0);
    reduce_act_kernel<<<(B_ * H2_) / 1024, blk, 0, s1>>>(
        p2, b2, c2, B_ * H2_, H2_ - 1);
    sgemm_nn_kernel<<<dim3(H1_ / 64, B_ / 64), blk, 0, s1>>>(
        c2, W2, b3, c3, B_, H1_, H2_);
    c3_frag_kernel<<<(32 * 32) / 8, blk, 0, s1>>>(c3, c3_frag);
    recover_mma_kernel<<<dim3(D_ / 256, B_ / 128), blk, 0, s1>>>(
        c3_frag, b_frag, b_r, recover);
    cudaEventRecord(aux.etail, s1);

    // s0: jac (s1p direct; s2p from p2 in-kernel)
    cudaStreamWaitEvent(s0, aux.ew, 0);
    jac_mma_kernel<<<dim3(D_ / 256, B_), blk, 0, s0>>>(
        w2f, s1p, p2, b2, b_frag, jac);

    // join
    cudaStreamWaitEvent(s0, aux.etail, 0);
}